// round 11
// baseline (speedup 1.0000x reference)
#include <cuda_runtime.h>
#include <cuda_fp16.h>
#include <math.h>

#define NN 500000
#define NE 4000000
#define TAB 2048

// Persistent device scratch (allocation-free rule: __device__ globals).
// Edge-view row: 32 halves = 64B.  [u:0-8 | q:8-16 | v:16-24 | p:24-32]
//   col side reads bytes 0..31 (u,q) in ONE 256-bit load; row side bytes 32..63 (v,p).
__device__ __align__(128) __half g_ev[NN * 32];   // 32MB
// Fused accumulator row: 8 halves = 16B per node (ai+ao merged).
__device__ __align__(128) __half g_acc[NN * 8];   // 8MB
// xc (fp32), node-pass linear access only
__device__ __align__(16)  float g_xc[NN * 12];    // 24MB
__device__ __align__(16)  float2 g_tab[TAB + 8];  // tanh LUT (value, central slope)
__device__ __align__(16)  int2 g_ei[NE];          // packed (row, col)  32MB

// ---------------- tanh via shared-memory lerp LUT ----------------
__device__ __forceinline__ float tanh_lut(float x, const float2* t) {
    float s = fmaf(x, 128.0f, 1024.0f);
    s = fminf(fmaxf(s, 0.0f), 2047.0f);
    float m = s + 12582912.0f;              // 1.5*2^23 round trick
    int i = __float_as_int(m) & 0x7FF;
    float f = s - (m - 12582912.0f);        // frac in [-0.5, 0.5]
    float2 e = t[i];
    return fmaf(f, e.y, e.x);
}

// one 16B RED carrying 8 fp16 values (sm_90+)
__device__ __forceinline__ void red_h8(__half* p, unsigned a, unsigned b,
                                       unsigned c, unsigned d) {
    asm volatile("red.global.add.noftz.v4.f16x2 [%0], {%1, %2, %3, %4};"
                 :: "l"(p), "r"(a), "r"(b), "r"(c), "r"(d) : "memory");
}

// 256-bit gather (sm_100+): one instruction, one L1tex line touch for 32B
__device__ __forceinline__ void ldg256(const __half* p, uint4& a, uint4& b) {
    asm volatile("ld.global.nc.v8.b32 {%0,%1,%2,%3,%4,%5,%6,%7}, [%8];"
                 : "=r"(a.x), "=r"(a.y), "=r"(a.z), "=r"(a.w),
                   "=r"(b.x), "=r"(b.y), "=r"(b.z), "=r"(b.w)
                 : "l"(p));
}

__global__ void k_tab() {
    int i = blockIdx.x * blockDim.x + threadIdx.x;
    if (i <= TAB) {
        const float h = 1.0f / 128.0f;
        float xi = -8.0f + (float)i * h;
        g_tab[i] = make_float2(tanhf(xi), 0.5f * (tanhf(xi + h) - tanhf(xi - h)));
    }
}

__global__ void k_pack(const int* __restrict__ ei) {
    int i = blockIdx.x * blockDim.x + threadIdx.x;
    if (i < NE) g_ei[i] = make_int2(ei[i], ei[NE + i]);
}

// o1[j] = bias[j] + sum_k xc_k * w[k*8+j]      (rows 0..9)
// o2[j] =           sum_k xc_k * w[(10+k)*8+j] (rows 10..19)
__device__ __forceinline__ void proj2(const float* xc, const float* w,
                                      const float* bias, float* o1, float* o2) {
#pragma unroll
    for (int j = 0; j < 8; j++) { o1[j] = bias ? bias[j] : 0.0f; o2[j] = 0.0f; }
#pragma unroll
    for (int k = 0; k < 10; k++) {
        float xk = xc[k];
        float4 a0 = *(const float4*)(w + k * 8);
        float4 a1 = *(const float4*)(w + k * 8 + 4);
        float4 b0 = *(const float4*)(w + (10 + k) * 8);
        float4 b1 = *(const float4*)(w + (10 + k) * 8 + 4);
        o1[0] = fmaf(xk, a0.x, o1[0]); o1[1] = fmaf(xk, a0.y, o1[1]);
        o1[2] = fmaf(xk, a0.z, o1[2]); o1[3] = fmaf(xk, a0.w, o1[3]);
        o1[4] = fmaf(xk, a1.x, o1[4]); o1[5] = fmaf(xk, a1.y, o1[5]);
        o1[6] = fmaf(xk, a1.z, o1[6]); o1[7] = fmaf(xk, a1.w, o1[7]);
        o2[0] = fmaf(xk, b0.x, o2[0]); o2[1] = fmaf(xk, b0.y, o2[1]);
        o2[2] = fmaf(xk, b0.z, o2[2]); o2[3] = fmaf(xk, b0.w, o2[3]);
        o2[4] = fmaf(xk, b1.x, o2[4]); o2[5] = fmaf(xk, b1.y, o2[5]);
        o2[6] = fmaf(xk, b1.z, o2[6]); o2[7] = fmaf(xk, b1.w, o2[7]);
    }
}

// Compute u,v (edge MLP halves) and p,q (node-layer projections), pack 64B fp16 row.
__device__ __forceinline__ void store_ev(int n, const float* xc,
                                         const float* s_e1w, const float* s_e1b,
                                         const float* s_pw) {
    float u[8], v[8], p[8], q[8];
    proj2(xc, s_e1w, s_e1b, u, v);
    proj2(xc, s_pw, nullptr, p, q);
    union { __half2 h[16]; uint4 qd[4]; } row;
#pragma unroll
    for (int j = 0; j < 4; j++) {
        row.h[j]      = __float22half2_rn(make_float2(u[2*j], u[2*j+1]));
        row.h[4 + j]  = __float22half2_rn(make_float2(q[2*j], q[2*j+1]));
        row.h[8 + j]  = __float22half2_rn(make_float2(v[2*j], v[2*j+1]));
        row.h[12 + j] = __float22half2_rn(make_float2(p[2*j], p[2*j+1]));
    }
    uint4* o = (uint4*)(g_ev + (size_t)n * 32);
    o[0] = row.qd[0]; o[1] = row.qd[1]; o[2] = row.qd[2]; o[3] = row.qd[3];
}

// ---------------- init ----------------
__global__ void k_init(const float* __restrict__ x,
                       const float* __restrict__ win_w, const float* __restrict__ win_b,
                       const float* __restrict__ e1_w, const float* __restrict__ e1_b,
                       const float* __restrict__ n1_w) {
    __shared__ __align__(16) float s_w[352];
    __shared__ __align__(16) float2 s_tab[TAB];
    int tid = threadIdx.x;
    for (int i = tid; i < TAB; i += blockDim.x) s_tab[i] = g_tab[i];
    if (tid < 16) s_w[tid] = win_w[tid];
    if (tid >= 16 && tid < 24) s_w[tid] = win_b[tid - 16];
    for (int i = tid; i < 160; i += blockDim.x) s_w[24 + i] = e1_w[i];
    if (tid < 8) s_w[184 + tid] = e1_b[tid];
    for (int i = tid; i < 160; i += blockDim.x) s_w[192 + i] = n1_w[i];
    __syncthreads();

    int n = blockIdx.x * blockDim.x + tid;
    if (n >= NN) return;

    float2 X = ((const float2*)x)[n];
    float xc[10];
#pragma unroll
    for (int j = 0; j < 8; j++) {
        float a = fmaf(X.x, s_w[j], fmaf(X.y, s_w[8 + j], s_w[16 + j]));
        xc[j] = tanh_lut(a, s_tab);
    }
    xc[8] = X.x; xc[9] = X.y;

    *(uint4*)(g_acc + (size_t)n * 8) = make_uint4(0, 0, 0, 0);

    float* xrow = g_xc + (size_t)n * 12;
    *(float4*)xrow       = make_float4(xc[0], xc[1], xc[2], xc[3]);
    *(float4*)(xrow + 4) = make_float4(xc[4], xc[5], xc[6], xc[7]);
    *(float4*)(xrow + 8) = make_float4(xc[8], xc[9], 0.0f, 0.0f);

    store_ev(n, xc, s_w + 24, s_w + 184, s_w + 192);
}

// ---------------- edge pass ----------------
// e = sigmoid(w2 . tanh(u[c]+v[r]) + b2)
// iters: acc[c] += p[r]*e ; acc[r] += q[c]*e   |   final: out[i] = e
template <bool FINAL>
__global__ void k_edge(const float* __restrict__ e2_w, const float* __restrict__ e2_b,
                       float* __restrict__ out) {
    __shared__ __align__(16) float2 s_tab[TAB];
    __shared__ float s_w2[12];
    int tid = threadIdx.x;
    for (int i = tid; i < TAB; i += blockDim.x) s_tab[i] = g_tab[i];
    if (tid < 8) s_w2[tid] = e2_w[tid];
    if (tid == 8) s_w2[8] = e2_b[0];
    __syncthreads();

    float w0 = s_w2[0], w1 = s_w2[1], w2 = s_w2[2], w3 = s_w2[3];
    float w4 = s_w2[4], w5 = s_w2[5], w6 = s_w2[6], w7 = s_w2[7];
    float b2 = s_w2[8];

    int stride = gridDim.x * blockDim.x;
    for (int i = blockIdx.x * blockDim.x + tid; i < NE; i += stride) {
        int2 rc = g_ei[i];
        const __half* cb = g_ev + (size_t)rc.y * 32;  // col node: u,q
        const __half* rb = g_ev + (size_t)rc.x * 32;  // row node: v,p

        uint4 uq, qq, vq, pq;
        if (FINAL) {
            // final pass needs only u and v: one 16B load per endpoint
            uq = *(const uint4*)(cb);
            vq = *(const uint4*)(rb + 16);
        } else {
            // one 256-bit load per endpoint: (u,q) and (v,p)
            ldg256(cb, uq, qq);
            ldg256(rb + 16, vq, pq);
        }
        const __half2* uh = (const __half2*)&uq;
        const __half2* vh = (const __half2*)&vq;

        float2 t0 = __half22float2(__hadd2(uh[0], vh[0]));
        float2 t1 = __half22float2(__hadd2(uh[1], vh[1]));
        float2 t2 = __half22float2(__hadd2(uh[2], vh[2]));
        float2 t3 = __half22float2(__hadd2(uh[3], vh[3]));

        float z = b2;
        z = fmaf(tanh_lut(t0.x, s_tab), w0, z);
        z = fmaf(tanh_lut(t0.y, s_tab), w1, z);
        z = fmaf(tanh_lut(t1.x, s_tab), w2, z);
        z = fmaf(tanh_lut(t1.y, s_tab), w3, z);
        z = fmaf(tanh_lut(t2.x, s_tab), w4, z);
        z = fmaf(tanh_lut(t2.y, s_tab), w5, z);
        z = fmaf(tanh_lut(t3.x, s_tab), w6, z);
        z = fmaf(tanh_lut(t3.y, s_tab), w7, z);
        float e = fmaf(tanh_lut(0.5f * z, s_tab), 0.5f, 0.5f);  // sigmoid(z)

        if (FINAL) {
            out[i] = e;
        } else {
            const __half2* qh = (const __half2*)&qq;
            const __half2* ph = (const __half2*)&pq;

            __half2 eh = __float2half2_rn(e);
            __half2 pc0 = __hmul2(ph[0], eh), pc1 = __hmul2(ph[1], eh);
            __half2 pc2 = __hmul2(ph[2], eh), pc3 = __hmul2(ph[3], eh);
            __half2 qr0 = __hmul2(qh[0], eh), qr1 = __hmul2(qh[1], eh);
            __half2 qr2 = __hmul2(qh[2], eh), qr3 = __hmul2(qh[3], eh);

            red_h8(g_acc + (size_t)rc.y * 8,
                   *(unsigned*)&pc0, *(unsigned*)&pc1,
                   *(unsigned*)&pc2, *(unsigned*)&pc3);
            red_h8(g_acc + (size_t)rc.x * 8,
                   *(unsigned*)&qr0, *(unsigned*)&qr1,
                   *(unsigned*)&qr2, *(unsigned*)&qr3);
        }
    }
}

// ---------------- node pass ----------------
// a = n1b + acc + xc@n1w[20:30]; H = tanh(tanh(a)@n2 + b2); rebuild ev row.
__global__ void k_node(const float* __restrict__ e1_w, const float* __restrict__ e1_b,
                       const float* __restrict__ n1_w, const float* __restrict__ n1_b,
                       const float* __restrict__ n2_w, const float* __restrict__ n2_b) {
    __shared__ __align__(16) float s_w[488];
    __shared__ __align__(16) float2 s_tab[TAB];
    int tid = threadIdx.x;
    for (int i = tid; i < TAB; i += blockDim.x) s_tab[i] = g_tab[i];
    for (int i = tid; i < 80; i += blockDim.x) s_w[i] = n1_w[160 + i];
    if (tid < 8) s_w[80 + tid] = n1_b[tid];
    for (int i = tid; i < 64; i += blockDim.x) s_w[88 + i] = n2_w[i];
    if (tid < 8) s_w[152 + tid] = n2_b[tid];
    for (int i = tid; i < 160; i += blockDim.x) s_w[160 + i] = e1_w[i];
    if (tid < 8) s_w[320 + tid] = e1_b[tid];
    for (int i = tid; i < 160; i += blockDim.x) s_w[328 + i] = n1_w[i];
    __syncthreads();

    int n = blockIdx.x * blockDim.x + tid;
    if (n >= NN) return;

    uint4* arow = (uint4*)(g_acc + (size_t)n * 8);
    uint4 av = *arow;
    *arow = make_uint4(0, 0, 0, 0);                 // reset for next edge pass
    const __half2* ah = (const __half2*)&av;
    float2 A0 = __half22float2(ah[0]), A1 = __half22float2(ah[1]);
    float2 A2 = __half22float2(ah[2]), A3 = __half22float2(ah[3]);

    float* xrow = g_xc + (size_t)n * 12;
    float4 x0 = *(float4*)xrow, x1 = *(float4*)(xrow + 4);
    float2 xX = *(float2*)(xrow + 8);
    float xc[10] = {x0.x, x0.y, x0.z, x0.w, x1.x, x1.y, x1.z, x1.w, xX.x, xX.y};

    float a[8];
    a[0] = s_w[80] + A0.x; a[1] = s_w[81] + A0.y;
    a[2] = s_w[82] + A1.x; a[3] = s_w[83] + A1.y;
    a[4] = s_w[84] + A2.x; a[5] = s_w[85] + A2.y;
    a[6] = s_w[86] + A3.x; a[7] = s_w[87] + A3.y;
#pragma unroll
    for (int k = 0; k < 10; k++) {
        float mk = xc[k];
        float4 wA = *(const float4*)(s_w + k * 8);
        float4 wB = *(const float4*)(s_w + k * 8 + 4);
        a[0] = fmaf(mk, wA.x, a[0]); a[1] = fmaf(mk, wA.y, a[1]);
        a[2] = fmaf(mk, wA.z, a[2]); a[3] = fmaf(mk, wA.w, a[3]);
        a[4] = fmaf(mk, wB.x, a[4]); a[5] = fmaf(mk, wB.y, a[5]);
        a[6] = fmaf(mk, wB.z, a[6]); a[7] = fmaf(mk, wB.w, a[7]);
    }
    float h[8];
#pragma unroll
    for (int j = 0; j < 8; j++) h[j] = tanh_lut(a[j], s_tab);

    float g[8];
#pragma unroll
    for (int j = 0; j < 8; j++) g[j] = s_w[152 + j];
#pragma unroll
    for (int k = 0; k < 8; k++) {
        float hk = h[k];
        float4 wA = *(const float4*)(s_w + 88 + k * 8);
        float4 wB = *(const float4*)(s_w + 88 + k * 8 + 4);
        g[0] = fmaf(hk, wA.x, g[0]); g[1] = fmaf(hk, wA.y, g[1]);
        g[2] = fmaf(hk, wA.z, g[2]); g[3] = fmaf(hk, wA.w, g[3]);
        g[4] = fmaf(hk, wB.x, g[4]); g[5] = fmaf(hk, wB.y, g[5]);
        g[6] = fmaf(hk, wB.z, g[6]); g[7] = fmaf(hk, wB.w, g[7]);
    }

    float nc[10];
#pragma unroll
    for (int j = 0; j < 8; j++) nc[j] = tanh_lut(g[j], s_tab);
    nc[8] = xX.x; nc[9] = xX.y;

    *(float4*)xrow       = make_float4(nc[0], nc[1], nc[2], nc[3]);
    *(float4*)(xrow + 4) = make_float4(nc[4], nc[5], nc[6], nc[7]);

    store_ev(n, nc, s_w + 160, s_w + 320, s_w + 328);
}

extern "C" void kernel_launch(void* const* d_in, const int* in_sizes, int n_in,
                              void* d_out, int out_size) {
    const float* x     = (const float*)d_in[0];
    const int*   ei    = (const int*)d_in[1];
    const float* win_w = (const float*)d_in[2];
    const float* win_b = (const float*)d_in[3];
    const float* e1_w  = (const float*)d_in[4];
    const float* e1_b  = (const float*)d_in[5];
    const float* e2_w  = (const float*)d_in[6];
    const float* e2_b  = (const float*)d_in[7];
    const float* n1_w  = (const float*)d_in[8];
    const float* n1_b  = (const float*)d_in[9];
    const float* n2_w  = (const float*)d_in[10];
    const float* n2_b  = (const float*)d_in[11];
    float* out = (float*)d_out;

    k_tab<<<9, 256>>>();
    k_pack<<<(NE + 255) / 256, 256>>>(ei);
    k_init<<<(NN + 255) / 256, 256>>>(x, win_w, win_b, e1_w, e1_b, n1_w);
    for (int it = 0; it < 3; it++) {
        k_edge<false><<<2368, 256>>>(e2_w, e2_b, nullptr);
        k_node<<<(NN + 255) / 256, 256>>>(e1_w, e1_b, n1_w, n1_b, n2_w, n2_b);
    }
    k_edge<true><<<2368, 256>>>(e2_w, e2_b, out);
}

// round 12
// speedup vs baseline: 1.2861x; 1.2861x over previous
#include <cuda_runtime.h>
#include <cuda_fp16.h>
#include <math.h>

#define NN 500000
#define NE 4000000

// Persistent device scratch (allocation-free rule: __device__ globals).
// Edge-view row: 32 halves = 64B.  [u:0-8 | q:8-16 | v:16-24 | p:24-32]
//   col side reads bytes 0..31 (u,q) in ONE 256-bit load; row side bytes 32..63 (v,p).
__device__ __align__(128) __half g_ev[NN * 32];   // 32MB
// Fused accumulator row: 8 halves = 16B per node (ai+ao merged).
__device__ __align__(128) __half g_acc[NN * 8];   // 8MB
// xc (fp32), node-pass linear access only
__device__ __align__(16)  float g_xc[NN * 12];    // 24MB
__device__ __align__(16)  int2 g_ei[NE];          // packed (row, col)  32MB

// ---------------- fast transcendentals (MUFU pipe, no smem) ----------------
__device__ __forceinline__ float tanh_fast(float x) {
    float y;
    asm("tanh.approx.f32 %0, %1;" : "=f"(y) : "f"(x));
    return y;
}
// sigmoid via ex2.approx (err ~2^-22 rel) + rcp.approx (err ~2^-14)
__device__ __forceinline__ float sigmoid_fast(float z) {
    float t, r;
    asm("ex2.approx.f32 %0, %1;" : "=f"(t) : "f"(z * -1.4426950408889634f));
    asm("rcp.approx.f32 %0, %1;" : "=f"(r) : "f"(1.0f + t));
    return r;
}

// one 16B RED carrying 8 fp16 values (sm_90+)
__device__ __forceinline__ void red_h8(__half* p, unsigned a, unsigned b,
                                       unsigned c, unsigned d) {
    asm volatile("red.global.add.noftz.v4.f16x2 [%0], {%1, %2, %3, %4};"
                 :: "l"(p), "r"(a), "r"(b), "r"(c), "r"(d) : "memory");
}

// 256-bit gather (sm_100+): one instruction for a 32B block
__device__ __forceinline__ void ldg256(const __half* p, uint4& a, uint4& b) {
    asm volatile("ld.global.nc.v8.b32 {%0,%1,%2,%3,%4,%5,%6,%7}, [%8];"
                 : "=r"(a.x), "=r"(a.y), "=r"(a.z), "=r"(a.w),
                   "=r"(b.x), "=r"(b.y), "=r"(b.z), "=r"(b.w)
                 : "l"(p));
}

__global__ void k_pack(const int* __restrict__ ei) {
    int i = blockIdx.x * blockDim.x + threadIdx.x;
    if (i < NE) g_ei[i] = make_int2(ei[i], ei[NE + i]);
}

// o1[j] = bias[j] + sum_k xc_k * w[k*8+j]      (rows 0..9)
// o2[j] =           sum_k xc_k * w[(10+k)*8+j] (rows 10..19)
__device__ __forceinline__ void proj2(const float* xc, const float* w,
                                      const float* bias, float* o1, float* o2) {
#pragma unroll
    for (int j = 0; j < 8; j++) { o1[j] = bias ? bias[j] : 0.0f; o2[j] = 0.0f; }
#pragma unroll
    for (int k = 0; k < 10; k++) {
        float xk = xc[k];
        float4 a0 = *(const float4*)(w + k * 8);
        float4 a1 = *(const float4*)(w + k * 8 + 4);
        float4 b0 = *(const float4*)(w + (10 + k) * 8);
        float4 b1 = *(const float4*)(w + (10 + k) * 8 + 4);
        o1[0] = fmaf(xk, a0.x, o1[0]); o1[1] = fmaf(xk, a0.y, o1[1]);
        o1[2] = fmaf(xk, a0.z, o1[2]); o1[3] = fmaf(xk, a0.w, o1[3]);
        o1[4] = fmaf(xk, a1.x, o1[4]); o1[5] = fmaf(xk, a1.y, o1[5]);
        o1[6] = fmaf(xk, a1.z, o1[6]); o1[7] = fmaf(xk, a1.w, o1[7]);
        o2[0] = fmaf(xk, b0.x, o2[0]); o2[1] = fmaf(xk, b0.y, o2[1]);
        o2[2] = fmaf(xk, b0.z, o2[2]); o2[3] = fmaf(xk, b0.w, o2[3]);
        o2[4] = fmaf(xk, b1.x, o2[4]); o2[5] = fmaf(xk, b1.y, o2[5]);
        o2[6] = fmaf(xk, b1.z, o2[6]); o2[7] = fmaf(xk, b1.w, o2[7]);
    }
}

// Compute u,v (edge MLP halves) and p,q (node-layer projections), pack 64B fp16 row.
__device__ __forceinline__ void store_ev(int n, const float* xc,
                                         const float* s_e1w, const float* s_e1b,
                                         const float* s_pw) {
    float u[8], v[8], p[8], q[8];
    proj2(xc, s_e1w, s_e1b, u, v);
    proj2(xc, s_pw, nullptr, p, q);
    union { __half2 h[16]; uint4 qd[4]; } row;
#pragma unroll
    for (int j = 0; j < 4; j++) {
        row.h[j]      = __float22half2_rn(make_float2(u[2*j], u[2*j+1]));
        row.h[4 + j]  = __float22half2_rn(make_float2(q[2*j], q[2*j+1]));
        row.h[8 + j]  = __float22half2_rn(make_float2(v[2*j], v[2*j+1]));
        row.h[12 + j] = __float22half2_rn(make_float2(p[2*j], p[2*j+1]));
    }
    uint4* o = (uint4*)(g_ev + (size_t)n * 32);
    o[0] = row.qd[0]; o[1] = row.qd[1]; o[2] = row.qd[2]; o[3] = row.qd[3];
}

// ---------------- init ----------------
__global__ void k_init(const float* __restrict__ x,
                       const float* __restrict__ win_w, const float* __restrict__ win_b,
                       const float* __restrict__ e1_w, const float* __restrict__ e1_b,
                       const float* __restrict__ n1_w) {
    __shared__ __align__(16) float s_w[352];
    int tid = threadIdx.x;
    if (tid < 16) s_w[tid] = win_w[tid];
    if (tid >= 16 && tid < 24) s_w[tid] = win_b[tid - 16];
    for (int i = tid; i < 160; i += blockDim.x) s_w[24 + i] = e1_w[i];
    if (tid < 8) s_w[184 + tid] = e1_b[tid];
    for (int i = tid; i < 160; i += blockDim.x) s_w[192 + i] = n1_w[i];
    __syncthreads();

    int n = blockIdx.x * blockDim.x + tid;
    if (n >= NN) return;

    float2 X = ((const float2*)x)[n];
    float xc[10];
#pragma unroll
    for (int j = 0; j < 8; j++) {
        float a = fmaf(X.x, s_w[j], fmaf(X.y, s_w[8 + j], s_w[16 + j]));
        xc[j] = tanh_fast(a);
    }
    xc[8] = X.x; xc[9] = X.y;

    *(uint4*)(g_acc + (size_t)n * 8) = make_uint4(0, 0, 0, 0);

    float* xrow = g_xc + (size_t)n * 12;
    *(float4*)xrow       = make_float4(xc[0], xc[1], xc[2], xc[3]);
    *(float4*)(xrow + 4) = make_float4(xc[4], xc[5], xc[6], xc[7]);
    *(float4*)(xrow + 8) = make_float4(xc[8], xc[9], 0.0f, 0.0f);

    store_ev(n, xc, s_w + 24, s_w + 184, s_w + 192);
}

// ---------------- edge pass ----------------
// e = sigmoid(w2 . tanh(u[c]+v[r]) + b2)
// iters: acc[c] += p[r]*e ; acc[r] += q[c]*e   |   final: out[i] = e
template <bool FINAL>
__global__ void k_edge(const float* __restrict__ e2_w, const float* __restrict__ e2_b,
                       float* __restrict__ out) {
    // weights via read-only cache (no smem, no barrier)
    float w0 = __ldg(e2_w + 0), w1 = __ldg(e2_w + 1);
    float w2 = __ldg(e2_w + 2), w3 = __ldg(e2_w + 3);
    float w4 = __ldg(e2_w + 4), w5 = __ldg(e2_w + 5);
    float w6 = __ldg(e2_w + 6), w7 = __ldg(e2_w + 7);
    float b2 = __ldg(e2_b);

    int stride = gridDim.x * blockDim.x;
    for (int i = blockIdx.x * blockDim.x + threadIdx.x; i < NE; i += stride) {
        int2 rc = g_ei[i];
        const __half* cb = g_ev + (size_t)rc.y * 32;  // col node: u,q
        const __half* rb = g_ev + (size_t)rc.x * 32;  // row node: v,p

        uint4 uq, qq, vq, pq;
        if (FINAL) {
            uq = *(const uint4*)(cb);
            vq = *(const uint4*)(rb + 16);
        } else {
            ldg256(cb, uq, qq);
            ldg256(rb + 16, vq, pq);
        }
        const __half2* uh = (const __half2*)&uq;
        const __half2* vh = (const __half2*)&vq;

        float2 t0 = __half22float2(__hadd2(uh[0], vh[0]));
        float2 t1 = __half22float2(__hadd2(uh[1], vh[1]));
        float2 t2 = __half22float2(__hadd2(uh[2], vh[2]));
        float2 t3 = __half22float2(__hadd2(uh[3], vh[3]));

        float z = b2;
        z = fmaf(tanh_fast(t0.x), w0, z);
        z = fmaf(tanh_fast(t0.y), w1, z);
        z = fmaf(tanh_fast(t1.x), w2, z);
        z = fmaf(tanh_fast(t1.y), w3, z);
        z = fmaf(tanh_fast(t2.x), w4, z);
        z = fmaf(tanh_fast(t2.y), w5, z);
        z = fmaf(tanh_fast(t3.x), w6, z);
        z = fmaf(tanh_fast(t3.y), w7, z);
        float e = sigmoid_fast(z);

        if (FINAL) {
            out[i] = e;
        } else {
            const __half2* qh = (const __half2*)&qq;
            const __half2* ph = (const __half2*)&pq;

            __half2 eh = __float2half2_rn(e);
            __half2 pc0 = __hmul2(ph[0], eh), pc1 = __hmul2(ph[1], eh);
            __half2 pc2 = __hmul2(ph[2], eh), pc3 = __hmul2(ph[3], eh);
            __half2 qr0 = __hmul2(qh[0], eh), qr1 = __hmul2(qh[1], eh);
            __half2 qr2 = __hmul2(qh[2], eh), qr3 = __hmul2(qh[3], eh);

            red_h8(g_acc + (size_t)rc.y * 8,
                   *(unsigned*)&pc0, *(unsigned*)&pc1,
                   *(unsigned*)&pc2, *(unsigned*)&pc3);
            red_h8(g_acc + (size_t)rc.x * 8,
                   *(unsigned*)&qr0, *(unsigned*)&qr1,
                   *(unsigned*)&qr2, *(unsigned*)&qr3);
        }
    }
}

// ---------------- node pass ----------------
// a = n1b + acc + xc@n1w[20:30]; H = tanh(tanh(a)@n2 + b2); rebuild ev row.
__global__ void k_node(const float* __restrict__ e1_w, const float* __restrict__ e1_b,
                       const float* __restrict__ n1_w, const float* __restrict__ n1_b,
                       const float* __restrict__ n2_w, const float* __restrict__ n2_b) {
    __shared__ __align__(16) float s_w[488];
    int tid = threadIdx.x;
    for (int i = tid; i < 80; i += blockDim.x) s_w[i] = n1_w[160 + i];
    if (tid < 8) s_w[80 + tid] = n1_b[tid];
    for (int i = tid; i < 64; i += blockDim.x) s_w[88 + i] = n2_w[i];
    if (tid < 8) s_w[152 + tid] = n2_b[tid];
    for (int i = tid; i < 160; i += blockDim.x) s_w[160 + i] = e1_w[i];
    if (tid < 8) s_w[320 + tid] = e1_b[tid];
    for (int i = tid; i < 160; i += blockDim.x) s_w[328 + i] = n1_w[i];
    __syncthreads();

    int n = blockIdx.x * blockDim.x + tid;
    if (n >= NN) return;

    uint4* arow = (uint4*)(g_acc + (size_t)n * 8);
    uint4 av = *arow;
    *arow = make_uint4(0, 0, 0, 0);                 // reset for next edge pass
    const __half2* ah = (const __half2*)&av;
    float2 A0 = __half22float2(ah[0]), A1 = __half22float2(ah[1]);
    float2 A2 = __half22float2(ah[2]), A3 = __half22float2(ah[3]);

    float* xrow = g_xc + (size_t)n * 12;
    float4 x0 = *(float4*)xrow, x1 = *(float4*)(xrow + 4);
    float2 xX = *(float2*)(xrow + 8);
    float xc[10] = {x0.x, x0.y, x0.z, x0.w, x1.x, x1.y, x1.z, x1.w, xX.x, xX.y};

    float a[8];
    a[0] = s_w[80] + A0.x; a[1] = s_w[81] + A0.y;
    a[2] = s_w[82] + A1.x; a[3] = s_w[83] + A1.y;
    a[4] = s_w[84] + A2.x; a[5] = s_w[85] + A2.y;
    a[6] = s_w[86] + A3.x; a[7] = s_w[87] + A3.y;
#pragma unroll
    for (int k = 0; k < 10; k++) {
        float mk = xc[k];
        float4 wA = *(const float4*)(s_w + k * 8);
        float4 wB = *(const float4*)(s_w + k * 8 + 4);
        a[0] = fmaf(mk, wA.x, a[0]); a[1] = fmaf(mk, wA.y, a[1]);
        a[2] = fmaf(mk, wA.z, a[2]); a[3] = fmaf(mk, wA.w, a[3]);
        a[4] = fmaf(mk, wB.x, a[4]); a[5] = fmaf(mk, wB.y, a[5]);
        a[6] = fmaf(mk, wB.z, a[6]); a[7] = fmaf(mk, wB.w, a[7]);
    }
    float h[8];
#pragma unroll
    for (int j = 0; j < 8; j++) h[j] = tanh_fast(a[j]);

    float g[8];
#pragma unroll
    for (int j = 0; j < 8; j++) g[j] = s_w[152 + j];
#pragma unroll
    for (int k = 0; k < 8; k++) {
        float hk = h[k];
        float4 wA = *(const float4*)(s_w + 88 + k * 8);
        float4 wB = *(const float4*)(s_w + 88 + k * 8 + 4);
        g[0] = fmaf(hk, wA.x, g[0]); g[1] = fmaf(hk, wA.y, g[1]);
        g[2] = fmaf(hk, wA.z, g[2]); g[3] = fmaf(hk, wA.w, g[3]);
        g[4] = fmaf(hk, wB.x, g[4]); g[5] = fmaf(hk, wB.y, g[5]);
        g[6] = fmaf(hk, wB.z, g[6]); g[7] = fmaf(hk, wB.w, g[7]);
    }

    float nc[10];
#pragma unroll
    for (int j = 0; j < 8; j++) nc[j] = tanh_fast(g[j]);
    nc[8] = xX.x; nc[9] = xX.y;

    *(float4*)xrow       = make_float4(nc[0], nc[1], nc[2], nc[3]);
    *(float4*)(xrow + 4) = make_float4(nc[4], nc[5], nc[6], nc[7]);

    store_ev(n, nc, s_w + 160, s_w + 320, s_w + 328);
}

extern "C" void kernel_launch(void* const* d_in, const int* in_sizes, int n_in,
                              void* d_out, int out_size) {
    const float* x     = (const float*)d_in[0];
    const int*   ei    = (const int*)d_in[1];
    const float* win_w = (const float*)d_in[2];
    const float* win_b = (const float*)d_in[3];
    const float* e1_w  = (const float*)d_in[4];
    const float* e1_b  = (const float*)d_in[5];
    const float* e2_w  = (const float*)d_in[6];
    const float* e2_b  = (const float*)d_in[7];
    const float* n1_w  = (const float*)d_in[8];
    const float* n1_b  = (const float*)d_in[9];
    const float* n2_w  = (const float*)d_in[10];
    const float* n2_b  = (const float*)d_in[11];
    float* out = (float*)d_out;

    k_pack<<<(NE + 255) / 256, 256>>>(ei);
    k_init<<<(NN + 255) / 256, 256>>>(x, win_w, win_b, e1_w, e1_b, n1_w);
    for (int it = 0; it < 3; it++) {
        k_edge<false><<<2368, 256>>>(e2_w, e2_b, nullptr);
        k_node<<<(NN + 255) / 256, 256>>>(e1_w, e1_b, n1_w, n1_b, n2_w, n2_b);
    }
    k_edge<true><<<2368, 256>>>(e2_w, e2_b, out);
}

// round 13
// speedup vs baseline: 1.4087x; 1.0954x over previous
#include <cuda_runtime.h>
#include <cuda_fp16.h>
#include <math.h>

#define NN 500000
#define NE 4000000

// Persistent device scratch (allocation-free rule: __device__ globals).
// Edge-view row: 32 halves = 64B.  [u:0-8 | q:8-16 | v:16-24 | p:24-32]
//   col side reads bytes 0..31 (u,q) in ONE 256-bit load; row side bytes 32..63 (v,p).
__device__ __align__(128) __half g_ev[NN * 32];   // 32MB
// Fused accumulator row: 8 halves = 16B per node (ai+ao merged).
__device__ __align__(128) __half g_acc[NN * 8];   // 8MB
// xc (fp32), node-pass linear access only
__device__ __align__(16)  float g_xc[NN * 12];    // 24MB

// ---------------- fast transcendentals (MUFU pipe, no smem) ----------------
__device__ __forceinline__ float tanh_fast(float x) {
    float y;
    asm("tanh.approx.f32 %0, %1;" : "=f"(y) : "f"(x));
    return y;
}
__device__ __forceinline__ float sigmoid_fast(float z) {
    float t, r;
    asm("ex2.approx.f32 %0, %1;" : "=f"(t) : "f"(z * -1.4426950408889634f));
    asm("rcp.approx.f32 %0, %1;" : "=f"(r) : "f"(1.0f + t));
    return r;
}

// one 16B RED carrying 8 fp16 values (sm_90+)
__device__ __forceinline__ void red_h8(__half* p, unsigned a, unsigned b,
                                       unsigned c, unsigned d) {
    asm volatile("red.global.add.noftz.v4.f16x2 [%0], {%1, %2, %3, %4};"
                 :: "l"(p), "r"(a), "r"(b), "r"(c), "r"(d) : "memory");
}

// 256-bit gather (sm_100+): one instruction for a 32B block
__device__ __forceinline__ void ldg256(const __half* p, uint4& a, uint4& b) {
    asm volatile("ld.global.nc.v8.b32 {%0,%1,%2,%3,%4,%5,%6,%7}, [%8];"
                 : "=r"(a.x), "=r"(a.y), "=r"(a.z), "=r"(a.w),
                   "=r"(b.x), "=r"(b.y), "=r"(b.z), "=r"(b.w)
                 : "l"(p));
}

// o1[j] = bias[j] + sum_k xc_k * w[k*8+j]      (rows 0..9)
// o2[j] =           sum_k xc_k * w[(10+k)*8+j] (rows 10..19)
__device__ __forceinline__ void proj2(const float* xc, const float* w,
                                      const float* bias, float* o1, float* o2) {
#pragma unroll
    for (int j = 0; j < 8; j++) { o1[j] = bias ? bias[j] : 0.0f; o2[j] = 0.0f; }
#pragma unroll
    for (int k = 0; k < 10; k++) {
        float xk = xc[k];
        float4 a0 = *(const float4*)(w + k * 8);
        float4 a1 = *(const float4*)(w + k * 8 + 4);
        float4 b0 = *(const float4*)(w + (10 + k) * 8);
        float4 b1 = *(const float4*)(w + (10 + k) * 8 + 4);
        o1[0] = fmaf(xk, a0.x, o1[0]); o1[1] = fmaf(xk, a0.y, o1[1]);
        o1[2] = fmaf(xk, a0.z, o1[2]); o1[3] = fmaf(xk, a0.w, o1[3]);
        o1[4] = fmaf(xk, a1.x, o1[4]); o1[5] = fmaf(xk, a1.y, o1[5]);
        o1[6] = fmaf(xk, a1.z, o1[6]); o1[7] = fmaf(xk, a1.w, o1[7]);
        o2[0] = fmaf(xk, b0.x, o2[0]); o2[1] = fmaf(xk, b0.y, o2[1]);
        o2[2] = fmaf(xk, b0.z, o2[2]); o2[3] = fmaf(xk, b0.w, o2[3]);
        o2[4] = fmaf(xk, b1.x, o2[4]); o2[5] = fmaf(xk, b1.y, o2[5]);
        o2[6] = fmaf(xk, b1.z, o2[6]); o2[7] = fmaf(xk, b1.w, o2[7]);
    }
}

// Pack 64B fp16 row. Sequential phases to cap live registers:
// phase 1: u,v (e1w) -> convert -> store o[0], o[2]
// phase 2: p,q (n1w rows 0..19) -> convert -> store o[1], o[3]
__device__ __forceinline__ void store_ev(int n, const float* xc,
                                         const float* s_e1w, const float* s_e1b,
                                         const float* s_pw) {
    uint4* o = (uint4*)(g_ev + (size_t)n * 32);
    {
        float u[8], v[8];
        proj2(xc, s_e1w, s_e1b, u, v);
        union { __half2 h[8]; uint4 qd[2]; } r1;
#pragma unroll
        for (int j = 0; j < 4; j++) {
            r1.h[j]     = __float22half2_rn(make_float2(u[2*j], u[2*j+1]));
            r1.h[4 + j] = __float22half2_rn(make_float2(v[2*j], v[2*j+1]));
        }
        o[0] = r1.qd[0];   // u
        o[2] = r1.qd[1];   // v
    }
    {
        float p[8], q[8];
        proj2(xc, s_pw, nullptr, p, q);
        union { __half2 h[8]; uint4 qd[2]; } r2;
#pragma unroll
        for (int j = 0; j < 4; j++) {
            r2.h[j]     = __float22half2_rn(make_float2(q[2*j], q[2*j+1]));
            r2.h[4 + j] = __float22half2_rn(make_float2(p[2*j], p[2*j+1]));
        }
        o[1] = r2.qd[0];   // q
        o[3] = r2.qd[1];   // p
    }
}

// ---------------- init ----------------
__global__ void k_init(const float* __restrict__ x,
                       const float* __restrict__ win_w, const float* __restrict__ win_b,
                       const float* __restrict__ e1_w, const float* __restrict__ e1_b,
                       const float* __restrict__ n1_w) {
    __shared__ __align__(16) float s_w[352];
    int tid = threadIdx.x;
    int n = blockIdx.x * blockDim.x + tid;
    float2 X = make_float2(0.0f, 0.0f);
    if (n < NN) X = ((const float2*)x)[n];     // issue load before smem fill

    if (tid < 16) s_w[tid] = win_w[tid];
    if (tid >= 16 && tid < 24) s_w[tid] = win_b[tid - 16];
    for (int i = tid; i < 160; i += blockDim.x) s_w[24 + i] = e1_w[i];
    if (tid < 8) s_w[184 + tid] = e1_b[tid];
    for (int i = tid; i < 160; i += blockDim.x) s_w[192 + i] = n1_w[i];
    __syncthreads();

    if (n >= NN) return;

    float xc[10];
#pragma unroll
    for (int j = 0; j < 8; j++) {
        float a = fmaf(X.x, s_w[j], fmaf(X.y, s_w[8 + j], s_w[16 + j]));
        xc[j] = tanh_fast(a);
    }
    xc[8] = X.x; xc[9] = X.y;

    *(uint4*)(g_acc + (size_t)n * 8) = make_uint4(0, 0, 0, 0);

    float* xrow = g_xc + (size_t)n * 12;
    *(float4*)xrow       = make_float4(xc[0], xc[1], xc[2], xc[3]);
    *(float4*)(xrow + 4) = make_float4(xc[4], xc[5], xc[6], xc[7]);
    *(float4*)(xrow + 8) = make_float4(xc[8], xc[9], 0.0f, 0.0f);

    store_ev(n, xc, s_w + 24, s_w + 184, s_w + 192);
}

// ---------------- edge pass ----------------
// e = sigmoid(w2 . tanh(u[c]+v[r]) + b2)
// iters: acc[c] += p[r]*e ; acc[r] += q[c]*e   |   final: out[i] = e
template <bool FINAL>
__global__ void k_edge(const int* __restrict__ ei,
                       const float* __restrict__ e2_w, const float* __restrict__ e2_b,
                       float* __restrict__ out) {
    float w0 = __ldg(e2_w + 0), w1 = __ldg(e2_w + 1);
    float w2 = __ldg(e2_w + 2), w3 = __ldg(e2_w + 3);
    float w4 = __ldg(e2_w + 4), w5 = __ldg(e2_w + 5);
    float w6 = __ldg(e2_w + 6), w7 = __ldg(e2_w + 7);
    float b2 = __ldg(e2_b);

    int stride = gridDim.x * blockDim.x;
    for (int i = blockIdx.x * blockDim.x + threadIdx.x; i < NE; i += stride) {
        int r = __ldg(ei + i);        // row
        int c = __ldg(ei + NE + i);   // col
        const __half* cb = g_ev + (size_t)c * 32;  // col node: u,q
        const __half* rb = g_ev + (size_t)r * 32;  // row node: v,p

        uint4 uq, qq, vq, pq;
        if (FINAL) {
            uq = *(const uint4*)(cb);
            vq = *(const uint4*)(rb + 16);
        } else {
            ldg256(cb, uq, qq);
            ldg256(rb + 16, vq, pq);
        }
        const __half2* uh = (const __half2*)&uq;
        const __half2* vh = (const __half2*)&vq;

        float2 t0 = __half22float2(__hadd2(uh[0], vh[0]));
        float2 t1 = __half22float2(__hadd2(uh[1], vh[1]));
        float2 t2 = __half22float2(__hadd2(uh[2], vh[2]));
        float2 t3 = __half22float2(__hadd2(uh[3], vh[3]));

        float z = b2;
        z = fmaf(tanh_fast(t0.x), w0, z);
        z = fmaf(tanh_fast(t0.y), w1, z);
        z = fmaf(tanh_fast(t1.x), w2, z);
        z = fmaf(tanh_fast(t1.y), w3, z);
        z = fmaf(tanh_fast(t2.x), w4, z);
        z = fmaf(tanh_fast(t2.y), w5, z);
        z = fmaf(tanh_fast(t3.x), w6, z);
        z = fmaf(tanh_fast(t3.y), w7, z);
        float e = sigmoid_fast(z);

        if (FINAL) {
            out[i] = e;
        } else {
            const __half2* qh = (const __half2*)&qq;
            const __half2* ph = (const __half2*)&pq;

            __half2 eh = __float2half2_rn(e);
            __half2 pc0 = __hmul2(ph[0], eh), pc1 = __hmul2(ph[1], eh);
            __half2 pc2 = __hmul2(ph[2], eh), pc3 = __hmul2(ph[3], eh);
            __half2 qr0 = __hmul2(qh[0], eh), qr1 = __hmul2(qh[1], eh);
            __half2 qr2 = __hmul2(qh[2], eh), qr3 = __hmul2(qh[3], eh);

            red_h8(g_acc + (size_t)c * 8,
                   *(unsigned*)&pc0, *(unsigned*)&pc1,
                   *(unsigned*)&pc2, *(unsigned*)&pc3);
            red_h8(g_acc + (size_t)r * 8,
                   *(unsigned*)&qr0, *(unsigned*)&qr1,
                   *(unsigned*)&qr2, *(unsigned*)&qr3);
        }
    }
}

// ---------------- node pass ----------------
// a = n1b + acc + xc@n1w[20:30]; H = tanh(tanh(a)@n2 + b2); rebuild ev row.
__global__ __launch_bounds__(256, 5)
void k_node(const float* __restrict__ e1_w, const float* __restrict__ e1_b,
            const float* __restrict__ n1_w, const float* __restrict__ n1_b,
            const float* __restrict__ n2_w, const float* __restrict__ n2_b) {
    __shared__ __align__(16) float s_w[488];
    int tid = threadIdx.x;
    int n = blockIdx.x * blockDim.x + tid;

    // issue per-node global loads before the smem fill so latency overlaps
    uint4 av = make_uint4(0, 0, 0, 0);
    float4 x0 = make_float4(0, 0, 0, 0), x1 = x0;
    float2 xX = make_float2(0, 0);
    uint4* arow = (uint4*)(g_acc + (size_t)n * 8);
    float* xrow = g_xc + (size_t)n * 12;
    if (n < NN) {
        av = *arow;
        x0 = *(float4*)xrow; x1 = *(float4*)(xrow + 4); xX = *(float2*)(xrow + 8);
    }

    for (int i = tid; i < 80; i += blockDim.x) s_w[i] = n1_w[160 + i];
    if (tid < 8) s_w[80 + tid] = n1_b[tid];
    for (int i = tid; i < 64; i += blockDim.x) s_w[88 + i] = n2_w[i];
    if (tid < 8) s_w[152 + tid] = n2_b[tid];
    for (int i = tid; i < 160; i += blockDim.x) s_w[160 + i] = e1_w[i];
    if (tid < 8) s_w[320 + tid] = e1_b[tid];
    for (int i = tid; i < 160; i += blockDim.x) s_w[328 + i] = n1_w[i];
    __syncthreads();

    if (n >= NN) return;

    *arow = make_uint4(0, 0, 0, 0);                 // reset for next edge pass
    const __half2* ah = (const __half2*)&av;
    float2 A0 = __half22float2(ah[0]), A1 = __half22float2(ah[1]);
    float2 A2 = __half22float2(ah[2]), A3 = __half22float2(ah[3]);

    float xc[10] = {x0.x, x0.y, x0.z, x0.w, x1.x, x1.y, x1.z, x1.w, xX.x, xX.y};

    float a[8];
    a[0] = s_w[80] + A0.x; a[1] = s_w[81] + A0.y;
    a[2] = s_w[82] + A1.x; a[3] = s_w[83] + A1.y;
    a[4] = s_w[84] + A2.x; a[5] = s_w[85] + A2.y;
    a[6] = s_w[86] + A3.x; a[7] = s_w[87] + A3.y;
#pragma unroll
    for (int k = 0; k < 10; k++) {
        float mk = xc[k];
        float4 wA = *(const float4*)(s_w + k * 8);
        float4 wB = *(const float4*)(s_w + k * 8 + 4);
        a[0] = fmaf(mk, wA.x, a[0]); a[1] = fmaf(mk, wA.y, a[1]);
        a[2] = fmaf(mk, wA.z, a[2]); a[3] = fmaf(mk, wA.w, a[3]);
        a[4] = fmaf(mk, wB.x, a[4]); a[5] = fmaf(mk, wB.y, a[5]);
        a[6] = fmaf(mk, wB.z, a[6]); a[7] = fmaf(mk, wB.w, a[7]);
    }
    float h[8];
#pragma unroll
    for (int j = 0; j < 8; j++) h[j] = tanh_fast(a[j]);

    float g[8];
#pragma unroll
    for (int j = 0; j < 8; j++) g[j] = s_w[152 + j];
#pragma unroll
    for (int k = 0; k < 8; k++) {
        float hk = h[k];
        float4 wA = *(const float4*)(s_w + 88 + k * 8);
        float4 wB = *(const float4*)(s_w + 88 + k * 8 + 4);
        g[0] = fmaf(hk, wA.x, g[0]); g[1] = fmaf(hk, wA.y, g[1]);
        g[2] = fmaf(hk, wA.z, g[2]); g[3] = fmaf(hk, wA.w, g[3]);
        g[4] = fmaf(hk, wB.x, g[4]); g[5] = fmaf(hk, wB.y, g[5]);
        g[6] = fmaf(hk, wB.z, g[6]); g[7] = fmaf(hk, wB.w, g[7]);
    }

    float nc[10];
#pragma unroll
    for (int j = 0; j < 8; j++) nc[j] = tanh_fast(g[j]);
    nc[8] = xX.x; nc[9] = xX.y;

    *(float4*)xrow       = make_float4(nc[0], nc[1], nc[2], nc[3]);
    *(float4*)(xrow + 4) = make_float4(nc[4], nc[5], nc[6], nc[7]);

    store_ev(n, nc, s_w + 160, s_w + 320, s_w + 328);
}

extern "C" void kernel_launch(void* const* d_in, const int* in_sizes, int n_in,
                              void* d_out, int out_size) {
    const float* x     = (const float*)d_in[0];
    const int*   ei    = (const int*)d_in[1];
    const float* win_w = (const float*)d_in[2];
    const float* win_b = (const float*)d_in[3];
    const float* e1_w  = (const float*)d_in[4];
    const float* e1_b  = (const float*)d_in[5];
    const float* e2_w  = (const float*)d_in[6];
    const float* e2_b  = (const float*)d_in[7];
    const float* n1_w  = (const float*)d_in[8];
    const float* n1_b  = (const float*)d_in[9];
    const float* n2_w  = (const float*)d_in[10];
    const float* n2_b  = (const float*)d_in[11];
    float* out = (float*)d_out;

    k_init<<<(NN + 255) / 256, 256>>>(x, win_w, win_b, e1_w, e1_b, n1_w);
    for (int it = 0; it < 3; it++) {
        k_edge<false><<<2368, 256>>>(ei, e2_w, e2_b, nullptr);
        k_node<<<(NN + 255) / 256, 256>>>(e1_w, e1_b, n1_w, n1_b, n2_w, n2_b);
    }
    k_edge<true><<<2368, 256>>>(ei, e2_w, e2_b, out);
}

// round 14
// speedup vs baseline: 1.4714x; 1.0445x over previous
#include <cuda_runtime.h>
#include <cuda_fp16.h>
#include <math.h>

#define NN 500000
#define NE 4000000

// Persistent device scratch (allocation-free rule: __device__ globals).
// Edge-view row: 32 halves = 64B.  [u:0-8 | q:8-16 | v:16-24 | p:24-32]
//   col side reads bytes 0..31 (u,q) in ONE 256-bit load; row side bytes 32..63 (v,p).
__device__ __align__(128) __half g_ev[NN * 32];   // 32MB
// Fused accumulator row: 8 halves = 16B per node (ai+ao merged).
__device__ __align__(128) __half g_acc[NN * 8];   // 8MB
// xc (fp32), node-pass linear access only
__device__ __align__(16)  float g_xc[NN * 12];    // 24MB

// ---------------- fast transcendentals (MUFU pipe, no smem) ----------------
__device__ __forceinline__ float tanh_fast(float x) {
    float y;
    asm("tanh.approx.f32 %0, %1;" : "=f"(y) : "f"(x));
    return y;
}
__device__ __forceinline__ float sigmoid_fast(float z) {
    float t, r;
    asm("ex2.approx.f32 %0, %1;" : "=f"(t) : "f"(z * -1.4426950408889634f));
    asm("rcp.approx.f32 %0, %1;" : "=f"(r) : "f"(1.0f + t));
    return r;
}

// one 16B RED carrying 8 fp16 values (sm_90+)
__device__ __forceinline__ void red_h8(__half* p, unsigned a, unsigned b,
                                       unsigned c, unsigned d) {
    asm volatile("red.global.add.noftz.v4.f16x2 [%0], {%1, %2, %3, %4};"
                 :: "l"(p), "r"(a), "r"(b), "r"(c), "r"(d) : "memory");
}

// 256-bit gather (sm_100+): one instruction for a 32B block
__device__ __forceinline__ void ldg256(const __half* p, uint4& a, uint4& b) {
    asm volatile("ld.global.nc.v8.b32 {%0,%1,%2,%3,%4,%5,%6,%7}, [%8];"
                 : "=r"(a.x), "=r"(a.y), "=r"(a.z), "=r"(a.w),
                   "=r"(b.x), "=r"(b.y), "=r"(b.z), "=r"(b.w)
                 : "l"(p));
}

// o1[j] = bias[j] + sum_k xc_k * w[k*8+j]      (rows 0..9)
// o2[j] =           sum_k xc_k * w[(10+k)*8+j] (rows 10..19)
__device__ __forceinline__ void proj2(const float* xc, const float* w,
                                      const float* bias, float* o1, float* o2) {
#pragma unroll
    for (int j = 0; j < 8; j++) { o1[j] = bias ? bias[j] : 0.0f; o2[j] = 0.0f; }
#pragma unroll
    for (int k = 0; k < 10; k++) {
        float xk = xc[k];
        float4 a0 = *(const float4*)(w + k * 8);
        float4 a1 = *(const float4*)(w + k * 8 + 4);
        float4 b0 = *(const float4*)(w + (10 + k) * 8);
        float4 b1 = *(const float4*)(w + (10 + k) * 8 + 4);
        o1[0] = fmaf(xk, a0.x, o1[0]); o1[1] = fmaf(xk, a0.y, o1[1]);
        o1[2] = fmaf(xk, a0.z, o1[2]); o1[3] = fmaf(xk, a0.w, o1[3]);
        o1[4] = fmaf(xk, a1.x, o1[4]); o1[5] = fmaf(xk, a1.y, o1[5]);
        o1[6] = fmaf(xk, a1.z, o1[6]); o1[7] = fmaf(xk, a1.w, o1[7]);
        o2[0] = fmaf(xk, b0.x, o2[0]); o2[1] = fmaf(xk, b0.y, o2[1]);
        o2[2] = fmaf(xk, b0.z, o2[2]); o2[3] = fmaf(xk, b0.w, o2[3]);
        o2[4] = fmaf(xk, b1.x, o2[4]); o2[5] = fmaf(xk, b1.y, o2[5]);
        o2[6] = fmaf(xk, b1.z, o2[6]); o2[7] = fmaf(xk, b1.w, o2[7]);
    }
}

// Pack fp16 edge-view row in two low-register phases.
// FULL=false writes only u (o[0]) and v (o[2]) — enough for the final edge pass.
template <bool FULL>
__device__ __forceinline__ void store_ev(int n, const float* xc,
                                         const float* s_e1w, const float* s_e1b,
                                         const float* s_pw) {
    uint4* o = (uint4*)(g_ev + (size_t)n * 32);
    {
        float u[8], v[8];
        proj2(xc, s_e1w, s_e1b, u, v);
        union { __half2 h[8]; uint4 qd[2]; } r1;
#pragma unroll
        for (int j = 0; j < 4; j++) {
            r1.h[j]     = __float22half2_rn(make_float2(u[2*j], u[2*j+1]));
            r1.h[4 + j] = __float22half2_rn(make_float2(v[2*j], v[2*j+1]));
        }
        o[0] = r1.qd[0];   // u
        o[2] = r1.qd[1];   // v
    }
    if (FULL) {
        float p[8], q[8];
        proj2(xc, s_pw, nullptr, p, q);
        union { __half2 h[8]; uint4 qd[2]; } r2;
#pragma unroll
        for (int j = 0; j < 4; j++) {
            r2.h[j]     = __float22half2_rn(make_float2(q[2*j], q[2*j+1]));
            r2.h[4 + j] = __float22half2_rn(make_float2(p[2*j], p[2*j+1]));
        }
        o[1] = r2.qd[0];   // q
        o[3] = r2.qd[1];   // p
    }
}

// ---------------- init ----------------
__global__ void k_init(const float* __restrict__ x,
                       const float* __restrict__ win_w, const float* __restrict__ win_b,
                       const float* __restrict__ e1_w, const float* __restrict__ e1_b,
                       const float* __restrict__ n1_w) {
    cudaTriggerProgrammaticLaunchCompletion();
    __shared__ __align__(16) float s_w[352];
    int tid = threadIdx.x;
    int n = blockIdx.x * blockDim.x + tid;
    float2 X = make_float2(0.0f, 0.0f);
    if (n < NN) X = ((const float2*)x)[n];     // issue load before smem fill

    if (tid < 16) s_w[tid] = win_w[tid];
    if (tid >= 16 && tid < 24) s_w[tid] = win_b[tid - 16];
    for (int i = tid; i < 160; i += blockDim.x) s_w[24 + i] = e1_w[i];
    if (tid < 8) s_w[184 + tid] = e1_b[tid];
    for (int i = tid; i < 160; i += blockDim.x) s_w[192 + i] = n1_w[i];
    __syncthreads();

    if (n >= NN) return;

    float xc[10];
#pragma unroll
    for (int j = 0; j < 8; j++) {
        float a = fmaf(X.x, s_w[j], fmaf(X.y, s_w[8 + j], s_w[16 + j]));
        xc[j] = tanh_fast(a);
    }
    xc[8] = X.x; xc[9] = X.y;

    *(uint4*)(g_acc + (size_t)n * 8) = make_uint4(0, 0, 0, 0);

    float* xrow = g_xc + (size_t)n * 12;
    *(float4*)xrow       = make_float4(xc[0], xc[1], xc[2], xc[3]);
    *(float4*)(xrow + 4) = make_float4(xc[4], xc[5], xc[6], xc[7]);
    *(float4*)(xrow + 8) = make_float4(xc[8], xc[9], 0.0f, 0.0f);

    store_ev<true>(n, xc, s_w + 24, s_w + 184, s_w + 192);
}

// ---------------- edge pass ----------------
// e = sigmoid(w2 . tanh(u[c]+v[r]) + b2)
// iters: acc[c] += p[r]*e ; acc[r] += q[c]*e   |   final: out[i] = e
template <bool FINAL>
__global__ void k_edge(const int* __restrict__ ei,
                       const float* __restrict__ e2_w, const float* __restrict__ e2_b,
                       float* __restrict__ out) {
    cudaTriggerProgrammaticLaunchCompletion();
    // input-only preamble: weights (read-only cache)
    float w0 = __ldg(e2_w + 0), w1 = __ldg(e2_w + 1);
    float w2 = __ldg(e2_w + 2), w3 = __ldg(e2_w + 3);
    float w4 = __ldg(e2_w + 4), w5 = __ldg(e2_w + 5);
    float w6 = __ldg(e2_w + 6), w7 = __ldg(e2_w + 7);
    float b2 = __ldg(e2_b);
    // wait for predecessor's g_ev / g_acc writes
    cudaGridDependencySynchronize();

    int stride = gridDim.x * blockDim.x;
    for (int i = blockIdx.x * blockDim.x + threadIdx.x; i < NE; i += stride) {
        int r = __ldg(ei + i);        // row
        int c = __ldg(ei + NE + i);   // col
        const __half* cb = g_ev + (size_t)c * 32;  // col node: u,q
        const __half* rb = g_ev + (size_t)r * 32;  // row node: v,p

        uint4 uq, qq, vq, pq;
        if (FINAL) {
            uq = *(const uint4*)(cb);
            vq = *(const uint4*)(rb + 16);
        } else {
            ldg256(cb, uq, qq);
            ldg256(rb + 16, vq, pq);
        }
        const __half2* uh = (const __half2*)&uq;
        const __half2* vh = (const __half2*)&vq;

        float2 t0 = __half22float2(__hadd2(uh[0], vh[0]));
        float2 t1 = __half22float2(__hadd2(uh[1], vh[1]));
        float2 t2 = __half22float2(__hadd2(uh[2], vh[2]));
        float2 t3 = __half22float2(__hadd2(uh[3], vh[3]));

        float z = b2;
        z = fmaf(tanh_fast(t0.x), w0, z);
        z = fmaf(tanh_fast(t0.y), w1, z);
        z = fmaf(tanh_fast(t1.x), w2, z);
        z = fmaf(tanh_fast(t1.y), w3, z);
        z = fmaf(tanh_fast(t2.x), w4, z);
        z = fmaf(tanh_fast(t2.y), w5, z);
        z = fmaf(tanh_fast(t3.x), w6, z);
        z = fmaf(tanh_fast(t3.y), w7, z);
        float e = sigmoid_fast(z);

        if (FINAL) {
            out[i] = e;
        } else {
            const __half2* qh = (const __half2*)&qq;
            const __half2* ph = (const __half2*)&pq;

            __half2 eh = __float2half2_rn(e);
            __half2 pc0 = __hmul2(ph[0], eh), pc1 = __hmul2(ph[1], eh);
            __half2 pc2 = __hmul2(ph[2], eh), pc3 = __hmul2(ph[3], eh);
            __half2 qr0 = __hmul2(qh[0], eh), qr1 = __hmul2(qh[1], eh);
            __half2 qr2 = __hmul2(qh[2], eh), qr3 = __hmul2(qh[3], eh);

            red_h8(g_acc + (size_t)c * 8,
                   *(unsigned*)&pc0, *(unsigned*)&pc1,
                   *(unsigned*)&pc2, *(unsigned*)&pc3);
            red_h8(g_acc + (size_t)r * 8,
                   *(unsigned*)&qr0, *(unsigned*)&qr1,
                   *(unsigned*)&qr2, *(unsigned*)&qr3);
        }
    }
}

// ---------------- node pass ----------------
// a = n1b + acc + xc@n1w[20:30]; H = tanh(tanh(a)@n2 + b2); rebuild ev row.
// LAST=true: final edge pass only needs u,v -> skip p,q, xc store, acc reset.
template <bool LAST>
__global__ __launch_bounds__(256, 5)
void k_node(const float* __restrict__ e1_w, const float* __restrict__ e1_b,
            const float* __restrict__ n1_w, const float* __restrict__ n1_b,
            const float* __restrict__ n2_w, const float* __restrict__ n2_b) {
    cudaTriggerProgrammaticLaunchCompletion();
    __shared__ __align__(16) float s_w[488];
    int tid = threadIdx.x;
    int n = blockIdx.x * blockDim.x + tid;

    // input-only preamble: weight fill (overlaps predecessor drain under PDL)
    for (int i = tid; i < 80; i += blockDim.x) s_w[i] = n1_w[160 + i];
    if (tid < 8) s_w[80 + tid] = n1_b[tid];
    for (int i = tid; i < 64; i += blockDim.x) s_w[88 + i] = n2_w[i];
    if (tid < 8) s_w[152 + tid] = n2_b[tid];
    for (int i = tid; i < 160; i += blockDim.x) s_w[160 + i] = e1_w[i];
    if (tid < 8) s_w[320 + tid] = e1_b[tid];
    for (int i = tid; i < 160; i += blockDim.x) s_w[328 + i] = n1_w[i];

    cudaGridDependencySynchronize();   // wait for edge pass's acc REDs
    __syncthreads();

    if (n >= NN) return;

    uint4* arow = (uint4*)(g_acc + (size_t)n * 8);
    float* xrow = g_xc + (size_t)n * 12;
    uint4 av = *arow;
    float4 x0 = *(float4*)xrow, x1 = *(float4*)(xrow + 4);
    float2 xX = *(float2*)(xrow + 8);
    if (!LAST) *arow = make_uint4(0, 0, 0, 0);      // reset for next edge pass

    const __half2* ah = (const __half2*)&av;
    float2 A0 = __half22float2(ah[0]), A1 = __half22float2(ah[1]);
    float2 A2 = __half22float2(ah[2]), A3 = __half22float2(ah[3]);

    float xc[10] = {x0.x, x0.y, x0.z, x0.w, x1.x, x1.y, x1.z, x1.w, xX.x, xX.y};

    float a[8];
    a[0] = s_w[80] + A0.x; a[1] = s_w[81] + A0.y;
    a[2] = s_w[82] + A1.x; a[3] = s_w[83] + A1.y;
    a[4] = s_w[84] + A2.x; a[5] = s_w[85] + A2.y;
    a[6] = s_w[86] + A3.x; a[7] = s_w[87] + A3.y;
#pragma unroll
    for (int k = 0; k < 10; k++) {
        float mk = xc[k];
        float4 wA = *(const float4*)(s_w + k * 8);
        float4 wB = *(const float4*)(s_w + k * 8 + 4);
        a[0] = fmaf(mk, wA.x, a[0]); a[1] = fmaf(mk, wA.y, a[1]);
        a[2] = fmaf(mk, wA.z, a[2]); a[3] = fmaf(mk, wA.w, a[3]);
        a[4] = fmaf(mk, wB.x, a[4]); a[5] = fmaf(mk, wB.y, a[5]);
        a[6] = fmaf(mk, wB.z, a[6]); a[7] = fmaf(mk, wB.w, a[7]);
    }
    float h[8];
#pragma unroll
    for (int j = 0; j < 8; j++) h[j] = tanh_fast(a[j]);

    float g[8];
#pragma unroll
    for (int j = 0; j < 8; j++) g[j] = s_w[152 + j];
#pragma unroll
    for (int k = 0; k < 8; k++) {
        float hk = h[k];
        float4 wA = *(const float4*)(s_w + 88 + k * 8);
        float4 wB = *(const float4*)(s_w + 88 + k * 8 + 4);
        g[0] = fmaf(hk, wA.x, g[0]); g[1] = fmaf(hk, wA.y, g[1]);
        g[2] = fmaf(hk, wA.z, g[2]); g[3] = fmaf(hk, wA.w, g[3]);
        g[4] = fmaf(hk, wB.x, g[4]); g[5] = fmaf(hk, wB.y, g[5]);
        g[6] = fmaf(hk, wB.z, g[6]); g[7] = fmaf(hk, wB.w, g[7]);
    }

    float nc[10];
#pragma unroll
    for (int j = 0; j < 8; j++) nc[j] = tanh_fast(g[j]);
    nc[8] = xX.x; nc[9] = xX.y;

    if (!LAST) {
        *(float4*)xrow       = make_float4(nc[0], nc[1], nc[2], nc[3]);
        *(float4*)(xrow + 4) = make_float4(nc[4], nc[5], nc[6], nc[7]);
    }

    store_ev<!LAST>(n, nc, s_w + 160, s_w + 320, s_w + 328);
}

extern "C" void kernel_launch(void* const* d_in, const int* in_sizes, int n_in,
                              void* d_out, int out_size) {
    const float* x     = (const float*)d_in[0];
    const int*   ei    = (const int*)d_in[1];
    const float* win_w = (const float*)d_in[2];
    const float* win_b = (const float*)d_in[3];
    const float* e1_w  = (const float*)d_in[4];
    const float* e1_b  = (const float*)d_in[5];
    const float* e2_w  = (const float*)d_in[6];
    const float* e2_b  = (const float*)d_in[7];
    const float* n1_w  = (const float*)d_in[8];
    const float* n1_b  = (const float*)d_in[9];
    const float* n2_w  = (const float*)d_in[10];
    const float* n2_b  = (const float*)d_in[11];
    float* out = (float*)d_out;

    // PDL launch config: successors may launch while predecessor drains
    cudaLaunchAttribute at[1];
    at[0].id = cudaLaunchAttributeProgrammaticStreamSerialization;
    at[0].val.programmaticStreamSerializationAllowed = 1;

    cudaLaunchConfig_t cfgE = {};
    cfgE.gridDim = dim3(2368); cfgE.blockDim = dim3(256);
    cfgE.attrs = at; cfgE.numAttrs = 1;

    cudaLaunchConfig_t cfgN = {};
    cfgN.gridDim = dim3((NN + 255) / 256); cfgN.blockDim = dim3(256);
    cfgN.attrs = at; cfgN.numAttrs = 1;

    k_init<<<(NN + 255) / 256, 256>>>(x, win_w, win_b, e1_w, e1_b, n1_w);
    for (int it = 0; it < 3; it++) {
        cudaLaunchKernelEx(&cfgE, k_edge<false>, ei, e2_w, e2_b, (float*)nullptr);
        if (it < 2)
            cudaLaunchKernelEx(&cfgN, k_node<false>, e1_w, e1_b, n1_w, n1_b, n2_w, n2_b);
        else
            cudaLaunchKernelEx(&cfgN, k_node<true>, e1_w, e1_b, n1_w, n1_b, n2_w, n2_b);
    }
    cudaLaunchKernelEx(&cfgE, k_edge<true>, ei, e2_w, e2_b, out);
}